// round 10
// baseline (speedup 1.0000x reference)
#include <cuda_runtime.h>
#include <cstdint>

// Shapes (fixed by the problem)
#define TT 1024   // tokens
#define HH 2048   // hidden
#define II 1024   // intermediate
#define EE 32     // experts
// GEMM tiling
#define BM 64
#define BN1 64    // g1 CTA N-tile (gate & up each)
#define BN2 128   // g2 CTA N-tile
#define BK 16     // K-slab per stage
#define ST 4      // pipeline stages (3 in flight)
#define RT 4      // tokens per router block

// ---------------- device scratch (static: no allocations allowed) ----------
__device__ int   g_cnt[EE];
__device__ int   g_tok [EE][TT];
__device__ float g_wt  [EE][TT];
__device__ int   g_prow[EE][TT];
__device__ float g_x[TT][HH];       // tf32-rounded activations: 8 MB
__device__ float g_h[TT * 2][II];   // tf32-rounded silu(g)*u*wt per pair: 8 MB

// ---------------- helpers ---------------------------------------------------
__device__ __forceinline__ uint32_t tf32r(float v) {
    uint32_t r;
    asm("cvt.rna.tf32.f32 %0, %1;" : "=r"(r) : "f"(v));
    return r;
}

__device__ __forceinline__ void mma_tf32(float* d, const uint32_t* a,
                                         uint32_t b0, uint32_t b1) {
    asm volatile(
        "mma.sync.aligned.m16n8k8.row.col.f32.tf32.tf32.f32 "
        "{%0,%1,%2,%3}, {%4,%5,%6,%7}, {%8,%9}, {%0,%1,%2,%3};\n"
        : "+f"(d[0]), "+f"(d[1]), "+f"(d[2]), "+f"(d[3])
        : "r"(a[0]), "r"(a[1]), "r"(a[2]), "r"(a[3]), "r"(b0), "r"(b1));
}

// 16B cp.async with zero-fill predicate (CUTLASS zfill form)
__device__ __forceinline__ void cp16(void* smem, const void* gmem, bool pred) {
    uint32_t sa = (uint32_t)__cvta_generic_to_shared(smem);
    int sz = pred ? 16 : 0;
    asm volatile("cp.async.cg.shared.global [%0], [%1], 16, %2;\n"
                 :: "r"(sa), "l"(gmem), "r"(sz));
}
__device__ __forceinline__ void cp_commit() {
    asm volatile("cp.async.commit_group;\n");
}

// ---------------- kernel 0: zero out + counters ------------------------------
__global__ __launch_bounds__(256)
void zero_kernel(float* __restrict__ out) {
    if (blockIdx.x == 0 && threadIdx.x < EE) g_cnt[threadIdx.x] = 0;
    const int i = blockIdx.x * 256 + threadIdx.x;   // TT*HH/4 float4s
    reinterpret_cast<float4*>(out)[i] = make_float4(0.f, 0.f, 0.f, 0.f);
}

// ---------------- kernel 1: router + tf32 pre-round of x ---------------------
__global__ __launch_bounds__(128)
void router_kernel(const float* __restrict__ x, const float* __restrict__ gw) {
    __shared__ float xs[RT][HH];     // 32 KB
    __shared__ float lg[RT][EE];

    const int t0 = blockIdx.x * RT;
    for (int i = threadIdx.x; i < RT * (HH / 4); i += 128) {
        const int rt = i >> 9;             // HH/4 = 512
        const int c  = i & 511;
        reinterpret_cast<float4*>(xs[rt])[c] =
            reinterpret_cast<const float4*>(x + (size_t)(t0 + rt) * HH)[c];
    }
    __syncthreads();

    // tf32-rounded copy of x for the GEMMs (removes cvt from GEMM A path)
    {
        const float* xf = &xs[0][0];
        float* gx = &g_x[t0][0];
        for (int i = threadIdx.x * 4; i < RT * HH; i += 128 * 4) {
            float4 v = *reinterpret_cast<const float4*>(xf + i);
            v.x = __uint_as_float(tf32r(v.x));
            v.y = __uint_as_float(tf32r(v.y));
            v.z = __uint_as_float(tf32r(v.z));
            v.w = __uint_as_float(tf32r(v.w));
            *reinterpret_cast<float4*>(gx + i) = v;
        }
    }

    const int warp = threadIdx.x >> 5, lane = threadIdx.x & 31;
    const float4* xv = reinterpret_cast<const float4*>(xs[warp]);
    for (int e = 0; e < EE; e++) {
        const float4* wv = reinterpret_cast<const float4*>(gw + (size_t)e * HH);
        float acc = 0.f;
        for (int k = lane; k < HH / 4; k += 32) {
            float4 a = xv[k], b = wv[k];
            acc += a.x * b.x + a.y * b.y + a.z * b.z + a.w * b.w;
        }
        #pragma unroll
        for (int o = 16; o; o >>= 1) acc += __shfl_xor_sync(0xffffffffu, acc, o);
        if (lane == 0) lg[warp][e] = acc;
    }
    if (lane == 0) {
        const int t = t0 + warp;
        float v0 = -1e30f, v1 = -1e30f; int i0 = 0, i1 = 0;
        for (int e = 0; e < EE; e++) {
            const float v = lg[warp][e];
            if (v > v0)      { v1 = v0; i1 = i0; v0 = v; i0 = e; }
            else if (v > v1) { v1 = v;  i1 = e; }
        }
        const float w0 = 1.f / (1.f + expf(v1 - v0));
        const float w1 = 1.f - w0;
        int s0 = atomicAdd(&g_cnt[i0], 1);
        g_tok[i0][s0] = t; g_wt[i0][s0] = w0; g_prow[i0][s0] = 2 * t;
        int s1 = atomicAdd(&g_cnt[i1], 1);
        g_tok[i1][s1] = t; g_wt[i1][s1] = w1; g_prow[i1][s1] = 2 * t + 1;
    }
}

// ============ 4-stage pipeline notes =========================================
// Row = BK=16 floats = 4 x 16B chunks. Chunk c of row r stored at c ^ ((r>>1)&3).
// Fragment reads: rows are base(mult of 8)+grp -> swizzle = grp>>1 (warp-level).
// Loop: one __syncthreads per iteration; wait_group 2 keeps 3 stages in flight.
// Buffer (kt+3)&3 was last read at iter kt-1, protected by the sync at iter kt.

// ---------------- kernel 2: fused gate&up GEMM + SwiGLU ----------------------
// grid = (II/BN1 = 16, EE * 16); 4 warps: 0-1 gate, 2-3 up, warp tile 64x32.
// smem: 4 stages x (A 4KB + Bg 4KB + Bu 4KB) = 48 KB.
__global__ __launch_bounds__(128, 4)
void moe_g1_kernel(const float* __restrict__ wg,
                   const float* __restrict__ wu) {
    const int e  = blockIdx.y >> 4;
    const int mt = blockIdx.y & 15;
    const int ne = g_cnt[e];
    if (mt * BM >= ne) return;
    const int nt = blockIdx.x;

    __shared__ float As[ST][BM][BK];
    __shared__ float Bg[ST][BN1][BK];
    __shared__ float Bu[ST][BN1][BK];

    const int tid  = threadIdx.x;
    const int lrow = tid & 63;          // loader row
    const int half = tid >> 6;          // chunk pair select
    const int lswz = (lrow >> 1) & 3;

    const int slot0 = mt * BM + lrow;
    const int tok0  = (slot0 < ne) ? g_tok[e][slot0] : -1;
    const int ta    = (tok0 < 0) ? 0 : tok0;

    const float* wgE = wg + ((size_t)e * II + (size_t)nt * BN1) * HH;
    const float* wuE = wu + ((size_t)e * II + (size_t)nt * BN1) * HH;

    auto load_stage = [&](int k0, int buf) {
        #pragma unroll
        for (int j = 0; j < 2; j++) {
            const int c  = 2 * half + j;
            const int pc = (c ^ lswz) << 2;
            cp16(&As[buf][lrow][pc], &g_x[ta][k0 + (c << 2)], tok0 >= 0);
            cp16(&Bg[buf][lrow][pc], wgE + (size_t)lrow * HH + k0 + (c << 2), true);
            cp16(&Bu[buf][lrow][pc], wuE + (size_t)lrow * HH + k0 + (c << 2), true);
        }
    };

    const int warp = tid >> 5, lane = tid & 31;
    const bool isGate = (warp < 2);
    const int wn  = (warp & 1) * 32;
    const int grp = lane >> 2, tg = lane & 3;
    const int sz  = grp >> 1;

    float acc[4][4][4];
    #pragma unroll
    for (int a = 0; a < 4; a++)
        #pragma unroll
        for (int b = 0; b < 4; b++)
            #pragma unroll
            for (int c = 0; c < 4; c++) acc[a][b][c] = 0.f;

    load_stage(0, 0);      cp_commit();
    load_stage(BK, 1);     cp_commit();
    load_stage(2 * BK, 2); cp_commit();

    const int NK = HH / BK;   // 128
    for (int kt = 0; kt < NK; kt++) {
        const int buf = kt & 3;
        asm volatile("cp.async.wait_group 2;\n");
        __syncthreads();

        const float* Bp = isGate ? &Bg[buf][0][0] : &Bu[buf][0][0];

        #pragma unroll
        for (int kk = 0; kk < BK; kk += 8) {
            const int w0 = ((((kk >> 2)    ) ^ sz) << 2) + tg;
            const int w1 = ((((kk >> 2) + 1) ^ sz) << 2) + tg;
            uint32_t a[4][4];
            #pragma unroll
            for (int mi = 0; mi < 4; mi++) {
                const int r0 = mi * 16 + grp, r1 = r0 + 8;
                a[mi][0] = __float_as_uint(As[buf][r0][w0]);
                a[mi][1] = __float_as_uint(As[buf][r1][w0]);
                a[mi][2] = __float_as_uint(As[buf][r0][w1]);
                a[mi][3] = __float_as_uint(As[buf][r1][w1]);
            }
            #pragma unroll
            for (int ni = 0; ni < 4; ni++) {
                const int col = wn + ni * 8 + grp;
                const uint32_t b0 = tf32r(Bp[col * BK + w0]);
                const uint32_t b1 = tf32r(Bp[col * BK + w1]);
                #pragma unroll
                for (int mi = 0; mi < 4; mi++)
                    mma_tf32(acc[mi][ni], a[mi], b0, b1);
            }
        }
        if (kt + 3 < NK) load_stage((kt + 3) * BK, (kt + 3) & 3);
        cp_commit();
    }

    // -------- epilogue: exchange u via smem, gate warps do SwiGLU ------------
    __syncthreads();   // all warps done reading As before it is reused as uex
    float (*uex)[BN1] = reinterpret_cast<float(*)[BN1]>(&As[0][0][0]);  // 16 KB

    if (!isGate) {
        #pragma unroll
        for (int mi = 0; mi < 4; mi++) {
            #pragma unroll
            for (int h2 = 0; h2 < 2; h2++) {
                const int row = mi * 16 + grp + h2 * 8;
                #pragma unroll
                for (int ni = 0; ni < 4; ni++) {
                    const int col = wn + ni * 8 + tg * 2;
                    uex[row][col    ] = acc[mi][ni][h2 * 2 + 0];
                    uex[row][col + 1] = acc[mi][ni][h2 * 2 + 1];
                }
            }
        }
    }
    __syncthreads();
    if (isGate) {
        #pragma unroll
        for (int mi = 0; mi < 4; mi++) {
            #pragma unroll
            for (int h2 = 0; h2 < 2; h2++) {
                const int rloc = mi * 16 + grp + h2 * 8;
                const int slot = mt * BM + rloc;
                if (slot >= ne) continue;
                const float wt = g_wt[e][slot];
                float* hrow = g_h[g_prow[e][slot]];
                #pragma unroll
                for (int ni = 0; ni < 4; ni++) {
                    const int col = wn + ni * 8 + tg * 2;
                    const float u0 = uex[rloc][col];
                    const float u1 = uex[rloc][col + 1];
                    const float gg0 = acc[mi][ni][h2 * 2 + 0];
                    const float gg1 = acc[mi][ni][h2 * 2 + 1];
                    const float h0 = gg0 / (1.f + __expf(-gg0)) * u0 * wt;
                    const float h1 = gg1 / (1.f + __expf(-gg1)) * u1 * wt;
                    *reinterpret_cast<float2*>(hrow + nt * BN1 + col) =
                        make_float2(__uint_as_float(tf32r(h0)),
                                    __uint_as_float(tf32r(h1)));
                }
            }
        }
    }
}

// ---------------- kernel 3: down_proj GEMM -> atomicAdd into out -------------
// grid = (HH/BN2 = 16, EE * 16); CTA tile 64x128, warp tile 32x64 (2x2 warps)
// smem: 4 stages x (A 4KB + B 8KB) = 48 KB.
// Each out element receives exactly 2 atomic contributions (one per expert);
// fp add is commutative, so the result is bit-deterministic.
__global__ __launch_bounds__(128, 4)
void moe_g2_kernel(const float* __restrict__ wd, float* __restrict__ out) {
    const int e  = blockIdx.y >> 4;
    const int mt = blockIdx.y & 15;
    const int ne = g_cnt[e];
    if (mt * BM >= ne) return;
    const int nt = blockIdx.x;

    __shared__ float As[ST][BM][BK];
    __shared__ float Bs[ST][BN2][BK];

    const int tid  = threadIdx.x;
    const int lrow = tid & 63;
    const int half = tid >> 6;
    const int aswz = (lrow >> 1) & 3;
    const int bswz = (tid >> 1) & 3;

    const int slot0 = mt * BM + lrow;
    const int pr0   = (slot0 < ne) ? g_prow[e][slot0] : -1;
    const int pa    = (pr0 < 0) ? 0 : pr0;

    const float* wdE = wd + ((size_t)e * HH + (size_t)nt * BN2) * II;

    auto load_stage = [&](int k0, int buf) {
        #pragma unroll
        for (int j = 0; j < 2; j++) {
            const int c  = 2 * half + j;
            const int pc = (c ^ aswz) << 2;
            cp16(&As[buf][lrow][pc], &g_h[pa][k0 + (c << 2)], pr0 >= 0);
        }
        #pragma unroll
        for (int c = 0; c < 4; c++) {
            const int pc = (c ^ bswz) << 2;
            cp16(&Bs[buf][tid][pc], wdE + (size_t)tid * II + k0 + (c << 2), true);
        }
    };

    const int warp = tid >> 5, lane = tid & 31;
    const int wm = (warp >> 1) * 32, wn = (warp & 1) * 64;
    const int grp = lane >> 2, tg = lane & 3;
    const int sz  = grp >> 1;

    float acc[2][8][4];
    #pragma unroll
    for (int a = 0; a < 2; a++)
        #pragma unroll
        for (int b = 0; b < 8; b++)
            #pragma unroll
            for (int c = 0; c < 4; c++) acc[a][b][c] = 0.f;

    load_stage(0, 0);      cp_commit();
    load_stage(BK, 1);     cp_commit();
    load_stage(2 * BK, 2); cp_commit();

    const int NK = II / BK;   // 64
    for (int kt = 0; kt < NK; kt++) {
        const int buf = kt & 3;
        asm volatile("cp.async.wait_group 2;\n");
        __syncthreads();

        #pragma unroll
        for (int kk = 0; kk < BK; kk += 8) {
            const int w0 = ((((kk >> 2)    ) ^ sz) << 2) + tg;
            const int w1 = ((((kk >> 2) + 1) ^ sz) << 2) + tg;
            uint32_t a[2][4];
            #pragma unroll
            for (int mi = 0; mi < 2; mi++) {
                const int r0 = wm + mi * 16 + grp, r1 = r0 + 8;
                a[mi][0] = __float_as_uint(As[buf][r0][w0]);
                a[mi][1] = __float_as_uint(As[buf][r1][w0]);
                a[mi][2] = __float_as_uint(As[buf][r0][w1]);
                a[mi][3] = __float_as_uint(As[buf][r1][w1]);
            }
            #pragma unroll
            for (int ni = 0; ni < 8; ni++) {
                const int col = wn + ni * 8 + grp;
                const uint32_t b0 = tf32r(Bs[buf][col][w0]);
                const uint32_t b1 = tf32r(Bs[buf][col][w1]);
                #pragma unroll
                for (int mi = 0; mi < 2; mi++)
                    mma_tf32(acc[mi][ni], a[mi], b0, b1);
            }
        }
        if (kt + 3 < NK) load_stage((kt + 3) * BK, (kt + 3) & 3);
        cp_commit();
    }

    // epilogue: atomic accumulate into out (2 contributions per element)
    #pragma unroll
    for (int mi = 0; mi < 2; mi++) {
        #pragma unroll
        for (int h2 = 0; h2 < 2; h2++) {
            const int rloc = wm + mi * 16 + grp + h2 * 8;
            const int slot = mt * BM + rloc;
            if (slot >= ne) continue;
            const int t = g_prow[e][slot] >> 1;
            float* orow = out + (size_t)t * HH + nt * BN2;
            #pragma unroll
            for (int ni = 0; ni < 8; ni++) {
                const int col = wn + ni * 8 + tg * 2;
                atomicAdd(orow + col,     acc[mi][ni][h2 * 2 + 0]);
                atomicAdd(orow + col + 1, acc[mi][ni][h2 * 2 + 1]);
            }
        }
    }
}

// ---------------- launch -----------------------------------------------------
extern "C" void kernel_launch(void* const* d_in, const int* in_sizes, int n_in,
                              void* d_out, int out_size) {
    const float* x  = (const float*)d_in[0];   // [T, H]
    const float* gw = (const float*)d_in[1];   // [E, H] router
    const float* wg = (const float*)d_in[2];   // [E, I, H] gate_proj
    const float* wu = (const float*)d_in[3];   // [E, I, H] up_proj
    const float* wd = (const float*)d_in[4];   // [E, H, I] down_proj
    float* out = (float*)d_out;                // [T, H]

    zero_kernel<<<(TT * HH / 4) / 256, 256>>>(out);
    router_kernel<<<TT / RT, 128>>>(x, gw);
    moe_g1_kernel<<<dim3(II / BN1, EE * 16), 128>>>(wg, wu);
    moe_g2_kernel<<<dim3(HH / BN2, EE * 16), 128>>>(wd, out);
}

// round 11
// speedup vs baseline: 1.8826x; 1.8826x over previous
#include <cuda_runtime.h>
#include <cstdint>

// Shapes (fixed by the problem)
#define TT 1024   // tokens
#define HH 2048   // hidden
#define II 1024   // intermediate
#define EE 32     // experts
// GEMM tiling
#define BM 64
#define BN1 64    // g1 CTA N-tile (gate & up each)
#define BN2 128   // g2 CTA N-tile
#define BK 32
#define RT 4      // tokens per router block

// ---------------- device scratch (static: no allocations allowed) ----------
__device__ int   g_cnt[EE];
__device__ int   g_tok [EE][TT];
__device__ float g_wt  [EE][TT];
__device__ int   g_prow[EE][TT];
__device__ float g_x[TT][HH];       // tf32-rounded activations: 8 MB
__device__ float g_h[TT * 2][II];   // tf32-rounded silu(g)*u*wt per pair: 8 MB

// ---------------- helpers ---------------------------------------------------
__device__ __forceinline__ uint32_t tf32r(float v) {
    uint32_t r;
    asm("cvt.rna.tf32.f32 %0, %1;" : "=r"(r) : "f"(v));
    return r;
}

__device__ __forceinline__ void mma_tf32(float* d, const uint32_t* a,
                                         uint32_t b0, uint32_t b1) {
    asm volatile(
        "mma.sync.aligned.m16n8k8.row.col.f32.tf32.tf32.f32 "
        "{%0,%1,%2,%3}, {%4,%5,%6,%7}, {%8,%9}, {%0,%1,%2,%3};\n"
        : "+f"(d[0]), "+f"(d[1]), "+f"(d[2]), "+f"(d[3])
        : "r"(a[0]), "r"(a[1]), "r"(a[2]), "r"(a[3]), "r"(b0), "r"(b1));
}

// 16B cp.async with zero-fill predicate (CUTLASS zfill form)
__device__ __forceinline__ void cp16(void* smem, const void* gmem, bool pred) {
    uint32_t sa = (uint32_t)__cvta_generic_to_shared(smem);
    int sz = pred ? 16 : 0;
    asm volatile("cp.async.cg.shared.global [%0], [%1], 16, %2;\n"
                 :: "r"(sa), "l"(gmem), "r"(sz));
}
__device__ __forceinline__ void cp_commit() {
    asm volatile("cp.async.commit_group;\n");
}

// ---------------- kernel 0: zero out + counters ------------------------------
__global__ __launch_bounds__(256)
void zero_kernel(float* __restrict__ out) {
    if (blockIdx.x == 0 && threadIdx.x < EE) g_cnt[threadIdx.x] = 0;
    const int i = blockIdx.x * 256 + threadIdx.x;   // TT*HH/4 float4s
    reinterpret_cast<float4*>(out)[i] = make_float4(0.f, 0.f, 0.f, 0.f);
}

// ---------------- kernel 1: router + tf32 pre-round of x ---------------------
__global__ __launch_bounds__(128)
void router_kernel(const float* __restrict__ x, const float* __restrict__ gw) {
    __shared__ float xs[RT][HH];     // 32 KB
    __shared__ float lg[RT][EE];

    const int t0 = blockIdx.x * RT;
    for (int i = threadIdx.x; i < RT * (HH / 4); i += 128) {
        const int rt = i >> 9;             // HH/4 = 512
        const int c  = i & 511;
        reinterpret_cast<float4*>(xs[rt])[c] =
            reinterpret_cast<const float4*>(x + (size_t)(t0 + rt) * HH)[c];
    }
    __syncthreads();

    // tf32-rounded copy of x for the GEMMs (removes cvt from GEMM A path)
    {
        const float* xf = &xs[0][0];
        float* gx = &g_x[t0][0];
        for (int i = threadIdx.x * 4; i < RT * HH; i += 128 * 4) {
            float4 v = *reinterpret_cast<const float4*>(xf + i);
            v.x = __uint_as_float(tf32r(v.x));
            v.y = __uint_as_float(tf32r(v.y));
            v.z = __uint_as_float(tf32r(v.z));
            v.w = __uint_as_float(tf32r(v.w));
            *reinterpret_cast<float4*>(gx + i) = v;
        }
    }

    const int warp = threadIdx.x >> 5, lane = threadIdx.x & 31;
    const float4* xv = reinterpret_cast<const float4*>(xs[warp]);
    for (int e = 0; e < EE; e++) {
        const float4* wv = reinterpret_cast<const float4*>(gw + (size_t)e * HH);
        float acc = 0.f;
        for (int k = lane; k < HH / 4; k += 32) {
            float4 a = xv[k], b = wv[k];
            acc += a.x * b.x + a.y * b.y + a.z * b.z + a.w * b.w;
        }
        #pragma unroll
        for (int o = 16; o; o >>= 1) acc += __shfl_xor_sync(0xffffffffu, acc, o);
        if (lane == 0) lg[warp][e] = acc;
    }
    if (lane == 0) {
        const int t = t0 + warp;
        float v0 = -1e30f, v1 = -1e30f; int i0 = 0, i1 = 0;
        for (int e = 0; e < EE; e++) {
            const float v = lg[warp][e];
            if (v > v0)      { v1 = v0; i1 = i0; v0 = v; i0 = e; }
            else if (v > v1) { v1 = v;  i1 = e; }
        }
        const float w0 = 1.f / (1.f + expf(v1 - v0));
        const float w1 = 1.f - w0;
        int s0 = atomicAdd(&g_cnt[i0], 1);
        g_tok[i0][s0] = t; g_wt[i0][s0] = w0; g_prow[i0][s0] = 2 * t;
        int s1 = atomicAdd(&g_cnt[i1], 1);
        g_tok[i1][s1] = t; g_wt[i1][s1] = w1; g_prow[i1][s1] = 2 * t + 1;
    }
}

// ---------------- kernel 2: fused gate&up GEMM + SwiGLU ----------------------
// grid = (II/BN1 = 16, EE * 16); CTA = 128 thr = 4 warps.
// CTA tile 64(M) x 64(N); warps 0-1 compute gate, warps 2-3 compute up,
// each with warp tile 64(M) x 32(N) on a single B matrix (1.5 ops/mma).
// smem: 2 stages x 3 tiles x 64x32 fp32 = 48 KB.
// Epilogue: up warps exchange u via smem (reusing As), gate warps do SwiGLU.
__global__ __launch_bounds__(128, 4)
void moe_g1_kernel(const float* __restrict__ wg,
                   const float* __restrict__ wu) {
    const int e  = blockIdx.y >> 4;
    const int mt = blockIdx.y & 15;
    const int ne = g_cnt[e];
    if (mt * BM >= ne) return;
    const int nt = blockIdx.x;

    __shared__ float As[2][BM][BK];
    __shared__ float Bg[2][BN1][BK];
    __shared__ float Bu[2][BN1][BK];

    const int tid = threadIdx.x;
    const int lr = tid >> 3;       // load row base (0..15)
    const int cw = tid & 7;        // 16B chunk (0..7)

    int tok[4];
    #pragma unroll
    for (int j = 0; j < 4; j++) {
        const int slot = mt * BM + lr + j * 16;
        tok[j] = (slot < ne) ? g_tok[e][slot] : -1;
    }

    const float* wgE = wg + ((size_t)e * II + (size_t)nt * BN1) * HH;
    const float* wuE = wu + ((size_t)e * II + (size_t)nt * BN1) * HH;

    auto load_stage = [&](int k0, int buf) {
        #pragma unroll
        for (int j = 0; j < 4; j++) {
            const int r  = lr + j * 16;
            const int sc = ((cw ^ (r & 7)) << 2);
            const int ta = (tok[j] < 0) ? 0 : tok[j];
            cp16(&As[buf][r][sc], &g_x[ta][k0 + (cw << 2)], tok[j] >= 0);
            cp16(&Bg[buf][r][sc], wgE + (size_t)r * HH + k0 + (cw << 2), true);
            cp16(&Bu[buf][r][sc], wuE + (size_t)r * HH + k0 + (cw << 2), true);
        }
    };

    const int warp = tid >> 5, lane = tid & 31;
    const bool isGate = (warp < 2);
    const int wn = (warp & 1) * 32;            // N offset within 64-wide tile
    const int grp = lane >> 2, tg = lane & 3;

    float acc[4][4][4];
    #pragma unroll
    for (int a = 0; a < 4; a++)
        #pragma unroll
        for (int b = 0; b < 4; b++)
            #pragma unroll
            for (int c = 0; c < 4; c++) acc[a][b][c] = 0.f;

    load_stage(0, 0); cp_commit();

    const int NK = HH / BK;   // 64
    for (int kt = 0; kt < NK; kt++) {
        const int buf = kt & 1;
        if (kt + 1 < NK) {
            load_stage((kt + 1) * BK, buf ^ 1); cp_commit();
            asm volatile("cp.async.wait_group 1;\n");
        } else {
            asm volatile("cp.async.wait_group 0;\n");
        }
        __syncthreads();

        const float* Bp = isGate ? &Bg[buf][0][0] : &Bu[buf][0][0];

        #pragma unroll
        for (int kk = 0; kk < BK; kk += 8) {
            // fragment rows/cols all have (idx & 7) == grp -> swizzle = ^grp
            const int c0 = (((kk >> 2)    ) ^ grp) << 2;
            const int c1 = (((kk >> 2) + 1) ^ grp) << 2;
            uint32_t a[4][4];
            #pragma unroll
            for (int mi = 0; mi < 4; mi++) {
                const int r0 = mi * 16 + grp, r1 = r0 + 8;
                a[mi][0] = __float_as_uint(As[buf][r0][c0 + tg]);
                a[mi][1] = __float_as_uint(As[buf][r1][c0 + tg]);
                a[mi][2] = __float_as_uint(As[buf][r0][c1 + tg]);
                a[mi][3] = __float_as_uint(As[buf][r1][c1 + tg]);
            }
            #pragma unroll
            for (int ni = 0; ni < 4; ni++) {
                const int col = wn + ni * 8 + grp;
                const uint32_t b0 = tf32r(Bp[col * BK + c0 + tg]);
                const uint32_t b1 = tf32r(Bp[col * BK + c1 + tg]);
                #pragma unroll
                for (int mi = 0; mi < 4; mi++)
                    mma_tf32(acc[mi][ni], a[mi], b0, b1);
            }
        }
        __syncthreads();
    }

    // -------- epilogue: exchange u via smem, gate warps do SwiGLU ------------
    // As (2*64*32 = 4096 floats) is dead; reuse as uex[64][64].
    float (*uex)[BN1] = reinterpret_cast<float(*)[BN1]>(&As[0][0][0]);

    if (!isGate) {
        #pragma unroll
        for (int mi = 0; mi < 4; mi++) {
            #pragma unroll
            for (int h2 = 0; h2 < 2; h2++) {
                const int row = mi * 16 + grp + h2 * 8;
                #pragma unroll
                for (int ni = 0; ni < 4; ni++) {
                    const int col = wn + ni * 8 + tg * 2;
                    uex[row][col    ] = acc[mi][ni][h2 * 2 + 0];
                    uex[row][col + 1] = acc[mi][ni][h2 * 2 + 1];
                }
            }
        }
    }
    __syncthreads();
    if (isGate) {
        #pragma unroll
        for (int mi = 0; mi < 4; mi++) {
            #pragma unroll
            for (int h2 = 0; h2 < 2; h2++) {
                const int rloc = mi * 16 + grp + h2 * 8;
                const int slot = mt * BM + rloc;
                if (slot >= ne) continue;
                const float wt = g_wt[e][slot];
                float* hrow = g_h[g_prow[e][slot]];
                #pragma unroll
                for (int ni = 0; ni < 4; ni++) {
                    const int col = wn + ni * 8 + tg * 2;
                    const float u0 = uex[rloc][col];
                    const float u1 = uex[rloc][col + 1];
                    const float gg0 = acc[mi][ni][h2 * 2 + 0];
                    const float gg1 = acc[mi][ni][h2 * 2 + 1];
                    const float h0 = gg0 / (1.f + __expf(-gg0)) * u0 * wt;
                    const float h1 = gg1 / (1.f + __expf(-gg1)) * u1 * wt;
                    *reinterpret_cast<float2*>(hrow + nt * BN1 + col) =
                        make_float2(__uint_as_float(tf32r(h0)),
                                    __uint_as_float(tf32r(h1)));
                }
            }
        }
    }
}

// ---------------- kernel 3: down_proj GEMM -> atomicAdd into out -------------
// grid = (HH/BN2 = 16, EE * 16); CTA tile 64x128, warp tile 32x64 (2x2 warps)
// smem: 2 x (64x32 + 128x32) fp32 = 48 KB.  A (g_h) pre-rounded -> no cvt.
// Each out element receives exactly 2 contributions; (0+a)+b == (0+b)+a in
// IEEE fp, so the result is bit-deterministic regardless of CTA order.
__global__ __launch_bounds__(128, 4)
void moe_g2_kernel(const float* __restrict__ wd, float* __restrict__ out) {
    const int e  = blockIdx.y >> 4;
    const int mt = blockIdx.y & 15;
    const int ne = g_cnt[e];
    if (mt * BM >= ne) return;
    const int nt = blockIdx.x;

    __shared__ float As[2][BM][BK];
    __shared__ float Bs[2][BN2][BK];

    const int tid = threadIdx.x;
    const int lr = tid >> 3;
    const int cw = tid & 7;

    int pr[4];
    #pragma unroll
    for (int j = 0; j < 4; j++) {
        const int slot = mt * BM + lr + j * 16;
        pr[j] = (slot < ne) ? g_prow[e][slot] : -1;
    }

    const float* wdE = wd + ((size_t)e * HH + (size_t)nt * BN2) * II;

    auto load_stage = [&](int k0, int buf) {
        #pragma unroll
        for (int j = 0; j < 4; j++) {
            const int r  = lr + j * 16;
            const int sc = ((cw ^ (r & 7)) << 2);
            const int pa = (pr[j] < 0) ? 0 : pr[j];
            cp16(&As[buf][r][sc], &g_h[pa][k0 + (cw << 2)], pr[j] >= 0);
        }
        #pragma unroll
        for (int j = 0; j < 8; j++) {
            const int r  = lr + j * 16;
            const int sc = ((cw ^ (r & 7)) << 2);
            cp16(&Bs[buf][r][sc], wdE + (size_t)r * II + k0 + (cw << 2), true);
        }
    };

    const int warp = tid >> 5, lane = tid & 31;
    const int wm = (warp >> 1) * 32, wn = (warp & 1) * 64;
    const int grp = lane >> 2, tg = lane & 3;

    float acc[2][8][4];
    #pragma unroll
    for (int a = 0; a < 2; a++)
        #pragma unroll
        for (int b = 0; b < 8; b++)
            #pragma unroll
            for (int c = 0; c < 4; c++) acc[a][b][c] = 0.f;

    load_stage(0, 0); cp_commit();

    const int NK = II / BK;   // 32
    for (int kt = 0; kt < NK; kt++) {
        const int buf = kt & 1;
        if (kt + 1 < NK) {
            load_stage((kt + 1) * BK, buf ^ 1); cp_commit();
            asm volatile("cp.async.wait_group 1;\n");
        } else {
            asm volatile("cp.async.wait_group 0;\n");
        }
        __syncthreads();

        #pragma unroll
        for (int kk = 0; kk < BK; kk += 8) {
            const int c0 = (((kk >> 2)    ) ^ grp) << 2;
            const int c1 = (((kk >> 2) + 1) ^ grp) << 2;
            uint32_t a[2][4];
            #pragma unroll
            for (int mi = 0; mi < 2; mi++) {
                const int r0 = wm + mi * 16 + grp, r1 = r0 + 8;
                a[mi][0] = __float_as_uint(As[buf][r0][c0 + tg]);
                a[mi][1] = __float_as_uint(As[buf][r1][c0 + tg]);
                a[mi][2] = __float_as_uint(As[buf][r0][c1 + tg]);
                a[mi][3] = __float_as_uint(As[buf][r1][c1 + tg]);
            }
            #pragma unroll
            for (int ni = 0; ni < 8; ni++) {
                const int col = wn + ni * 8 + grp;
                const uint32_t b0 = tf32r(Bs[buf][col][c0 + tg]);
                const uint32_t b1 = tf32r(Bs[buf][col][c1 + tg]);
                #pragma unroll
                for (int mi = 0; mi < 2; mi++)
                    mma_tf32(acc[mi][ni], a[mi], b0, b1);
            }
        }
        __syncthreads();
    }

    // epilogue: atomic accumulate into out (exactly 2 contributions/element)
    #pragma unroll
    for (int mi = 0; mi < 2; mi++) {
        #pragma unroll
        for (int h2 = 0; h2 < 2; h2++) {
            const int rloc = wm + mi * 16 + grp + h2 * 8;
            const int slot = mt * BM + rloc;
            if (slot >= ne) continue;
            const int t = g_prow[e][slot] >> 1;
            float* orow = out + (size_t)t * HH + nt * BN2;
            #pragma unroll
            for (int ni = 0; ni < 8; ni++) {
                const int col = wn + ni * 8 + tg * 2;
                atomicAdd(orow + col,     acc[mi][ni][h2 * 2 + 0]);
                atomicAdd(orow + col + 1, acc[mi][ni][h2 * 2 + 1]);
            }
        }
    }
}

// ---------------- launch -----------------------------------------------------
extern "C" void kernel_launch(void* const* d_in, const int* in_sizes, int n_in,
                              void* d_out, int out_size) {
    const float* x  = (const float*)d_in[0];   // [T, H]
    const float* gw = (const float*)d_in[1];   // [E, H] router
    const float* wg = (const float*)d_in[2];   // [E, I, H] gate_proj
    const float* wu = (const float*)d_in[3];   // [E, I, H] up_proj
    const float* wd = (const float*)d_in[4];   // [E, H, I] down_proj
    float* out = (float*)d_out;                // [T, H]

    zero_kernel<<<(TT * HH / 4) / 256, 256>>>(out);
    router_kernel<<<TT / RT, 128>>>(x, gw);
    moe_g1_kernel<<<dim3(II / BN1, EE * 16), 128>>>(wg, wu);
    moe_g2_kernel<<<dim3(HH / BN2, EE * 16), 128>>>(wd, out);
}

// round 13
// speedup vs baseline: 1.9555x; 1.0387x over previous
#include <cuda_runtime.h>
#include <cstdint>

// Shapes (fixed by the problem)
#define TT 1024   // tokens
#define HH 2048   // hidden
#define II 1024   // intermediate
#define EE 32     // experts
// GEMM tiling
#define BM1 32    // g1 CTA M-tile (fine-grained: less padding, more CTAs)
#define BM 64     // g2 CTA M-tile
#define BN1 64    // g1 CTA N-tile (gate & up each)
#define BN2 128   // g2 CTA N-tile
#define BK 32
#define RT 4      // tokens per router block

// ---------------- device scratch (static: no allocations allowed) ----------
__device__ int   g_cnt[EE];
__device__ int   g_tok [EE][TT];
__device__ float g_wt  [EE][TT];
__device__ int   g_prow[EE][TT];
__device__ float g_x[TT][HH];       // tf32-rounded activations: 8 MB
__device__ float g_h[TT * 2][II];   // tf32-rounded silu(g)*u*wt per pair: 8 MB

// ---------------- helpers ---------------------------------------------------
__device__ __forceinline__ uint32_t tf32r(float v) {
    uint32_t r;
    asm("cvt.rna.tf32.f32 %0, %1;" : "=r"(r) : "f"(v));
    return r;
}

__device__ __forceinline__ void mma_tf32(float* d, const uint32_t* a,
                                         uint32_t b0, uint32_t b1) {
    asm volatile(
        "mma.sync.aligned.m16n8k8.row.col.f32.tf32.tf32.f32 "
        "{%0,%1,%2,%3}, {%4,%5,%6,%7}, {%8,%9}, {%0,%1,%2,%3};\n"
        : "+f"(d[0]), "+f"(d[1]), "+f"(d[2]), "+f"(d[3])
        : "r"(a[0]), "r"(a[1]), "r"(a[2]), "r"(a[3]), "r"(b0), "r"(b1));
}

// 16B cp.async with zero-fill predicate (CUTLASS zfill form)
__device__ __forceinline__ void cp16(void* smem, const void* gmem, bool pred) {
    uint32_t sa = (uint32_t)__cvta_generic_to_shared(smem);
    int sz = pred ? 16 : 0;
    asm volatile("cp.async.cg.shared.global [%0], [%1], 16, %2;\n"
                 :: "r"(sa), "l"(gmem), "r"(sz));
}
__device__ __forceinline__ void cp_commit() {
    asm volatile("cp.async.commit_group;\n");
}

// ---------------- kernel 0: zero out + counters ------------------------------
__global__ __launch_bounds__(256)
void zero_kernel(float* __restrict__ out) {
    if (blockIdx.x == 0 && threadIdx.x < EE) g_cnt[threadIdx.x] = 0;
    const int i = blockIdx.x * 256 + threadIdx.x;   // TT*HH/4 float4s
    reinterpret_cast<float4*>(out)[i] = make_float4(0.f, 0.f, 0.f, 0.f);
}

// ---------------- kernel 1: router + tf32 pre-round of x ---------------------
__global__ __launch_bounds__(128)
void router_kernel(const float* __restrict__ x, const float* __restrict__ gw) {
    __shared__ float xs[RT][HH];     // 32 KB
    __shared__ float lg[RT][EE];

    const int t0 = blockIdx.x * RT;
    for (int i = threadIdx.x; i < RT * (HH / 4); i += 128) {
        const int rt = i >> 9;             // HH/4 = 512
        const int c  = i & 511;
        reinterpret_cast<float4*>(xs[rt])[c] =
            reinterpret_cast<const float4*>(x + (size_t)(t0 + rt) * HH)[c];
    }
    __syncthreads();

    // tf32-rounded copy of x for the GEMMs (removes cvt from GEMM A path)
    {
        const float* xf = &xs[0][0];
        float* gx = &g_x[t0][0];
        for (int i = threadIdx.x * 4; i < RT * HH; i += 128 * 4) {
            float4 v = *reinterpret_cast<const float4*>(xf + i);
            v.x = __uint_as_float(tf32r(v.x));
            v.y = __uint_as_float(tf32r(v.y));
            v.z = __uint_as_float(tf32r(v.z));
            v.w = __uint_as_float(tf32r(v.w));
            *reinterpret_cast<float4*>(gx + i) = v;
        }
    }

    const int warp = threadIdx.x >> 5, lane = threadIdx.x & 31;
    const float4* xv = reinterpret_cast<const float4*>(xs[warp]);
    for (int e = 0; e < EE; e++) {
        const float4* wv = reinterpret_cast<const float4*>(gw + (size_t)e * HH);
        float acc = 0.f;
        for (int k = lane; k < HH / 4; k += 32) {
            float4 a = xv[k], b = wv[k];
            acc += a.x * b.x + a.y * b.y + a.z * b.z + a.w * b.w;
        }
        #pragma unroll
        for (int o = 16; o; o >>= 1) acc += __shfl_xor_sync(0xffffffffu, acc, o);
        if (lane == 0) lg[warp][e] = acc;
    }
    if (lane == 0) {
        const int t = t0 + warp;
        float v0 = -1e30f, v1 = -1e30f; int i0 = 0, i1 = 0;
        for (int e = 0; e < EE; e++) {
            const float v = lg[warp][e];
            if (v > v0)      { v1 = v0; i1 = i0; v0 = v; i0 = e; }
            else if (v > v1) { v1 = v;  i1 = e; }
        }
        const float w0 = 1.f / (1.f + expf(v1 - v0));
        const float w1 = 1.f - w0;
        int s0 = atomicAdd(&g_cnt[i0], 1);
        g_tok[i0][s0] = t; g_wt[i0][s0] = w0; g_prow[i0][s0] = 2 * t;
        int s1 = atomicAdd(&g_cnt[i1], 1);
        g_tok[i1][s1] = t; g_wt[i1][s1] = w1; g_prow[i1][s1] = 2 * t + 1;
    }
}

// ---------------- kernel 2: fused gate&up GEMM + SwiGLU ----------------------
// grid = (II/BN1 = 16, EE * 32); CTA = 128 thr = 4 warps.
// CTA tile 32(M) x 64(N); warps 0-1 gate, warps 2-3 up, warp tile 32x32.
// smem: 2 stages x (A 32x32 + Bg 64x32 + Bu 64x32) fp32 = 40 KB -> 5 CTAs/SM.
// Epilogue: up warps exchange u via smem (reusing As = 8KB = uex[32][64]).
__global__ __launch_bounds__(128, 5)
void moe_g1_kernel(const float* __restrict__ wg,
                   const float* __restrict__ wu) {
    const int e  = blockIdx.y >> 5;
    const int mt = blockIdx.y & 31;
    const int ne = g_cnt[e];
    if (mt * BM1 >= ne) return;
    const int nt = blockIdx.x;

    __shared__ float As[2][BM1][BK];   // 8 KB
    __shared__ float Bg[2][BN1][BK];   // 16 KB
    __shared__ float Bu[2][BN1][BK];   // 16 KB

    const int tid = threadIdx.x;
    const int lr = tid >> 3;       // load row base (0..15)
    const int cw = tid & 7;        // 16B chunk (0..7)

    int tok[2];
    #pragma unroll
    for (int j = 0; j < 2; j++) {
        const int slot = mt * BM1 + lr + j * 16;
        tok[j] = (slot < ne) ? g_tok[e][slot] : -1;
    }

    const float* wgE = wg + ((size_t)e * II + (size_t)nt * BN1) * HH;
    const float* wuE = wu + ((size_t)e * II + (size_t)nt * BN1) * HH;

    auto load_stage = [&](int k0, int buf) {
        #pragma unroll
        for (int j = 0; j < 2; j++) {
            const int r  = lr + j * 16;
            const int sc = ((cw ^ (r & 7)) << 2);
            const int ta = (tok[j] < 0) ? 0 : tok[j];
            cp16(&As[buf][r][sc], &g_x[ta][k0 + (cw << 2)], tok[j] >= 0);
        }
        #pragma unroll
        for (int j = 0; j < 4; j++) {
            const int r  = lr + j * 16;
            const int sc = ((cw ^ (r & 7)) << 2);
            cp16(&Bg[buf][r][sc], wgE + (size_t)r * HH + k0 + (cw << 2), true);
            cp16(&Bu[buf][r][sc], wuE + (size_t)r * HH + k0 + (cw << 2), true);
        }
    };

    const int warp = tid >> 5, lane = tid & 31;
    const bool isGate = (warp < 2);
    const int wn = (warp & 1) * 32;            // N offset within 64-wide tile
    const int grp = lane >> 2, tg = lane & 3;

    float acc[2][4][4];
    #pragma unroll
    for (int a = 0; a < 2; a++)
        #pragma unroll
        for (int b = 0; b < 4; b++)
            #pragma unroll
            for (int c = 0; c < 4; c++) acc[a][b][c] = 0.f;

    load_stage(0, 0); cp_commit();

    const int NK = HH / BK;   // 64
    for (int kt = 0; kt < NK; kt++) {
        const int buf = kt & 1;
        if (kt + 1 < NK) {
            load_stage((kt + 1) * BK, buf ^ 1); cp_commit();
            asm volatile("cp.async.wait_group 1;\n");
        } else {
            asm volatile("cp.async.wait_group 0;\n");
        }
        __syncthreads();

        const float* Bp = isGate ? &Bg[buf][0][0] : &Bu[buf][0][0];

        #pragma unroll
        for (int kk = 0; kk < BK; kk += 8) {
            // fragment rows/cols all have (idx & 7) == grp -> swizzle = ^grp
            const int c0 = (((kk >> 2)    ) ^ grp) << 2;
            const int c1 = (((kk >> 2) + 1) ^ grp) << 2;
            uint32_t a[2][4];
            #pragma unroll
            for (int mi = 0; mi < 2; mi++) {
                const int r0 = mi * 16 + grp, r1 = r0 + 8;
                a[mi][0] = __float_as_uint(As[buf][r0][c0 + tg]);
                a[mi][1] = __float_as_uint(As[buf][r1][c0 + tg]);
                a[mi][2] = __float_as_uint(As[buf][r0][c1 + tg]);
                a[mi][3] = __float_as_uint(As[buf][r1][c1 + tg]);
            }
            #pragma unroll
            for (int ni = 0; ni < 4; ni++) {
                const int col = wn + ni * 8 + grp;
                const uint32_t b0 = tf32r(Bp[col * BK + c0 + tg]);
                const uint32_t b1 = tf32r(Bp[col * BK + c1 + tg]);
                #pragma unroll
                for (int mi = 0; mi < 2; mi++)
                    mma_tf32(acc[mi][ni], a[mi], b0, b1);
            }
        }
        __syncthreads();
    }

    // -------- epilogue: exchange u via smem, gate warps do SwiGLU ------------
    // As (2*32*32 = 2048 floats = 8KB) is dead; reuse as uex[32][64].
    float (*uex)[BN1] = reinterpret_cast<float(*)[BN1]>(&As[0][0][0]);

    if (!isGate) {
        #pragma unroll
        for (int mi = 0; mi < 2; mi++) {
            #pragma unroll
            for (int h2 = 0; h2 < 2; h2++) {
                const int row = mi * 16 + grp + h2 * 8;
                #pragma unroll
                for (int ni = 0; ni < 4; ni++) {
                    const int col = wn + ni * 8 + tg * 2;
                    uex[row][col    ] = acc[mi][ni][h2 * 2 + 0];
                    uex[row][col + 1] = acc[mi][ni][h2 * 2 + 1];
                }
            }
        }
    }
    __syncthreads();
    if (isGate) {
        #pragma unroll
        for (int mi = 0; mi < 2; mi++) {
            #pragma unroll
            for (int h2 = 0; h2 < 2; h2++) {
                const int rloc = mi * 16 + grp + h2 * 8;
                const int slot = mt * BM1 + rloc;
                if (slot >= ne) continue;
                const float wt = g_wt[e][slot];
                float* hrow = g_h[g_prow[e][slot]];
                #pragma unroll
                for (int ni = 0; ni < 4; ni++) {
                    const int col = wn + ni * 8 + tg * 2;
                    const float u0 = uex[rloc][col];
                    const float u1 = uex[rloc][col + 1];
                    const float gg0 = acc[mi][ni][h2 * 2 + 0];
                    const float gg1 = acc[mi][ni][h2 * 2 + 1];
                    const float h0 = gg0 / (1.f + __expf(-gg0)) * u0 * wt;
                    const float h1 = gg1 / (1.f + __expf(-gg1)) * u1 * wt;
                    *reinterpret_cast<float2*>(hrow + nt * BN1 + col) =
                        make_float2(__uint_as_float(tf32r(h0)),
                                    __uint_as_float(tf32r(h1)));
                }
            }
        }
    }
}

// ---------------- kernel 3: down_proj GEMM -> atomicAdd into out -------------
// grid = (HH/BN2 = 16, EE * 16); CTA tile 64x128, warp tile 32x64 (2x2 warps)
// smem: 2 x (64x32 + 128x32) fp32 = 48 KB.  A (g_h) pre-rounded -> no cvt.
// Each out element receives exactly 2 contributions; (0+a)+b == (0+b)+a in
// IEEE fp, so the result is bit-deterministic regardless of CTA order.
__global__ __launch_bounds__(128, 4)
void moe_g2_kernel(const float* __restrict__ wd, float* __restrict__ out) {
    const int e  = blockIdx.y >> 4;
    const int mt = blockIdx.y & 15;
    const int ne = g_cnt[e];
    if (mt * BM >= ne) return;
    const int nt = blockIdx.x;

    __shared__ float As[2][BM][BK];
    __shared__ float Bs[2][BN2][BK];

    const int tid = threadIdx.x;
    const int lr = tid >> 3;
    const int cw = tid & 7;

    int pr[4];
    #pragma unroll
    for (int j = 0; j < 4; j++) {
        const int slot = mt * BM + lr + j * 16;
        pr[j] = (slot < ne) ? g_prow[e][slot] : -1;
    }

    const float* wdE = wd + ((size_t)e * HH + (size_t)nt * BN2) * II;

    auto load_stage = [&](int k0, int buf) {
        #pragma unroll
        for (int j = 0; j < 4; j++) {
            const int r  = lr + j * 16;
            const int sc = ((cw ^ (r & 7)) << 2);
            const int pa = (pr[j] < 0) ? 0 : pr[j];
            cp16(&As[buf][r][sc], &g_h[pa][k0 + (cw << 2)], pr[j] >= 0);
        }
        #pragma unroll
        for (int j = 0; j < 8; j++) {
            const int r  = lr + j * 16;
            const int sc = ((cw ^ (r & 7)) << 2);
            cp16(&Bs[buf][r][sc], wdE + (size_t)r * II + k0 + (cw << 2), true);
        }
    };

    const int warp = tid >> 5, lane = tid & 31;
    const int wm = (warp >> 1) * 32, wn = (warp & 1) * 64;
    const int grp = lane >> 2, tg = lane & 3;

    float acc[2][8][4];
    #pragma unroll
    for (int a = 0; a < 2; a++)
        #pragma unroll
        for (int b = 0; b < 8; b++)
            #pragma unroll
            for (int c = 0; c < 4; c++) acc[a][b][c] = 0.f;

    load_stage(0, 0); cp_commit();

    const int NK = II / BK;   // 32
    for (int kt = 0; kt < NK; kt++) {
        const int buf = kt & 1;
        if (kt + 1 < NK) {
            load_stage((kt + 1) * BK, buf ^ 1); cp_commit();
            asm volatile("cp.async.wait_group 1;\n");
        } else {
            asm volatile("cp.async.wait_group 0;\n");
        }
        __syncthreads();

        #pragma unroll
        for (int kk = 0; kk < BK; kk += 8) {
            const int c0 = (((kk >> 2)    ) ^ grp) << 2;
            const int c1 = (((kk >> 2) + 1) ^ grp) << 2;
            uint32_t a[2][4];
            #pragma unroll
            for (int mi = 0; mi < 2; mi++) {
                const int r0 = wm + mi * 16 + grp, r1 = r0 + 8;
                a[mi][0] = __float_as_uint(As[buf][r0][c0 + tg]);
                a[mi][1] = __float_as_uint(As[buf][r1][c0 + tg]);
                a[mi][2] = __float_as_uint(As[buf][r0][c1 + tg]);
                a[mi][3] = __float_as_uint(As[buf][r1][c1 + tg]);
            }
            #pragma unroll
            for (int ni = 0; ni < 8; ni++) {
                const int col = wn + ni * 8 + grp;
                const uint32_t b0 = tf32r(Bs[buf][col][c0 + tg]);
                const uint32_t b1 = tf32r(Bs[buf][col][c1 + tg]);
                #pragma unroll
                for (int mi = 0; mi < 2; mi++)
                    mma_tf32(acc[mi][ni], a[mi], b0, b1);
            }
        }
        __syncthreads();
    }

    // epilogue: atomic accumulate into out (exactly 2 contributions/element)
    #pragma unroll
    for (int mi = 0; mi < 2; mi++) {
        #pragma unroll
        for (int h2 = 0; h2 < 2; h2++) {
            const int rloc = wm + mi * 16 + grp + h2 * 8;
            const int slot = mt * BM + rloc;
            if (slot >= ne) continue;
            const int t = g_prow[e][slot] >> 1;
            float* orow = out + (size_t)t * HH + nt * BN2;
            #pragma unroll
            for (int ni = 0; ni < 8; ni++) {
                const int col = wn + ni * 8 + tg * 2;
                atomicAdd(orow + col,     acc[mi][ni][h2 * 2 + 0]);
                atomicAdd(orow + col + 1, acc[mi][ni][h2 * 2 + 1]);
            }
        }
    }
}

// ---------------- launch -----------------------------------------------------
extern "C" void kernel_launch(void* const* d_in, const int* in_sizes, int n_in,
                              void* d_out, int out_size) {
    const float* x  = (const float*)d_in[0];   // [T, H]
    const float* gw = (const float*)d_in[1];   // [E, H] router
    const float* wg = (const float*)d_in[2];   // [E, I, H] gate_proj
    const float* wu = (const float*)d_in[3];   // [E, I, H] up_proj
    const float* wd = (const float*)d_in[4];   // [E, H, I] down_proj
    float* out = (float*)d_out;                // [T, H]

    zero_kernel<<<(TT * HH / 4) / 256, 256>>>(out);
    router_kernel<<<TT / RT, 128>>>(x, gw);
    moe_g1_kernel<<<dim3(II / BN1, EE * 32), 128>>>(wg, wu);
    moe_g2_kernel<<<dim3(HH / BN2, EE * 16), 128>>>(wd, out);
}

// round 15
// speedup vs baseline: 1.9999x; 1.0227x over previous
#include <cuda_runtime.h>
#include <cstdint>

// Shapes (fixed by the problem)
#define TT 1024   // tokens
#define HH 2048   // hidden
#define II 1024   // intermediate
#define EE 32     // experts
// GEMM tiling
#define BM1 32    // g1 CTA M-tile
#define BM2 32    // g2 CTA M-tile (fine-grained: less padding, more CTAs)
#define BN1 64    // g1 CTA N-tile (gate & up each)
#define BN2 128   // g2 CTA N-tile
#define BK 32
#define RT 4      // tokens per router block

// ---------------- device scratch (static: no allocations allowed) ----------
__device__ int   g_cnt[EE];
__device__ int   g_tok [EE][TT];
__device__ float g_wt  [EE][TT];
__device__ int   g_prow[EE][TT];
__device__ float g_x[TT][HH];       // tf32-rounded activations: 8 MB
__device__ float g_h[TT * 2][II];   // tf32-rounded silu(g)*u*wt per pair: 8 MB

// ---------------- helpers ---------------------------------------------------
__device__ __forceinline__ uint32_t tf32r(float v) {
    uint32_t r;
    asm("cvt.rna.tf32.f32 %0, %1;" : "=r"(r) : "f"(v));
    return r;
}

__device__ __forceinline__ void mma_tf32(float* d, const uint32_t* a,
                                         uint32_t b0, uint32_t b1) {
    asm volatile(
        "mma.sync.aligned.m16n8k8.row.col.f32.tf32.tf32.f32 "
        "{%0,%1,%2,%3}, {%4,%5,%6,%7}, {%8,%9}, {%0,%1,%2,%3};\n"
        : "+f"(d[0]), "+f"(d[1]), "+f"(d[2]), "+f"(d[3])
        : "r"(a[0]), "r"(a[1]), "r"(a[2]), "r"(a[3]), "r"(b0), "r"(b1));
}

// 16B cp.async with zero-fill predicate (CUTLASS zfill form)
__device__ __forceinline__ void cp16(void* smem, const void* gmem, bool pred) {
    uint32_t sa = (uint32_t)__cvta_generic_to_shared(smem);
    int sz = pred ? 16 : 0;
    asm volatile("cp.async.cg.shared.global [%0], [%1], 16, %2;\n"
                 :: "r"(sa), "l"(gmem), "r"(sz));
}
__device__ __forceinline__ void cp_commit() {
    asm volatile("cp.async.commit_group;\n");
}

// ---------------- kernel 0: zero out + counters ------------------------------
__global__ __launch_bounds__(256)
void zero_kernel(float* __restrict__ out) {
    if (blockIdx.x == 0 && threadIdx.x < EE) g_cnt[threadIdx.x] = 0;
    const int i = blockIdx.x * 256 + threadIdx.x;   // TT*HH/4 float4s
    reinterpret_cast<float4*>(out)[i] = make_float4(0.f, 0.f, 0.f, 0.f);
}

// ---------------- kernel 1: router + tf32 pre-round of x ---------------------
__global__ __launch_bounds__(128)
void router_kernel(const float* __restrict__ x, const float* __restrict__ gw) {
    __shared__ float xs[RT][HH];     // 32 KB
    __shared__ float lg[RT][EE];

    const int t0 = blockIdx.x * RT;
    for (int i = threadIdx.x; i < RT * (HH / 4); i += 128) {
        const int rt = i >> 9;             // HH/4 = 512
        const int c  = i & 511;
        reinterpret_cast<float4*>(xs[rt])[c] =
            reinterpret_cast<const float4*>(x + (size_t)(t0 + rt) * HH)[c];
    }
    __syncthreads();

    // tf32-rounded copy of x for the GEMMs (removes cvt from GEMM A path)
    {
        const float* xf = &xs[0][0];
        float* gx = &g_x[t0][0];
        for (int i = threadIdx.x * 4; i < RT * HH; i += 128 * 4) {
            float4 v = *reinterpret_cast<const float4*>(xf + i);
            v.x = __uint_as_float(tf32r(v.x));
            v.y = __uint_as_float(tf32r(v.y));
            v.z = __uint_as_float(tf32r(v.z));
            v.w = __uint_as_float(tf32r(v.w));
            *reinterpret_cast<float4*>(gx + i) = v;
        }
    }

    const int warp = threadIdx.x >> 5, lane = threadIdx.x & 31;
    const float4* xv = reinterpret_cast<const float4*>(xs[warp]);
    for (int e = 0; e < EE; e++) {
        const float4* wv = reinterpret_cast<const float4*>(gw + (size_t)e * HH);
        float acc = 0.f;
        for (int k = lane; k < HH / 4; k += 32) {
            float4 a = xv[k], b = wv[k];
            acc += a.x * b.x + a.y * b.y + a.z * b.z + a.w * b.w;
        }
        #pragma unroll
        for (int o = 16; o; o >>= 1) acc += __shfl_xor_sync(0xffffffffu, acc, o);
        if (lane == 0) lg[warp][e] = acc;
    }
    if (lane == 0) {
        const int t = t0 + warp;
        float v0 = -1e30f, v1 = -1e30f; int i0 = 0, i1 = 0;
        for (int e = 0; e < EE; e++) {
            const float v = lg[warp][e];
            if (v > v0)      { v1 = v0; i1 = i0; v0 = v; i0 = e; }
            else if (v > v1) { v1 = v;  i1 = e; }
        }
        const float w0 = 1.f / (1.f + expf(v1 - v0));
        const float w1 = 1.f - w0;
        int s0 = atomicAdd(&g_cnt[i0], 1);
        g_tok[i0][s0] = t; g_wt[i0][s0] = w0; g_prow[i0][s0] = 2 * t;
        int s1 = atomicAdd(&g_cnt[i1], 1);
        g_tok[i1][s1] = t; g_wt[i1][s1] = w1; g_prow[i1][s1] = 2 * t + 1;
    }
}

// ---------------- kernel 2: fused gate&up GEMM + SwiGLU ----------------------
// grid = (II/BN1 = 16, EE * 32); CTA = 128 thr = 4 warps.
// CTA tile 32(M) x 64(N); warps 0-1 gate, warps 2-3 up, warp tile 32x32.
// smem: 2 stages x (A 32x32 + Bg 64x32 + Bu 64x32) fp32 = 40 KB -> 5 CTAs/SM.
// Epilogue: up warps exchange u via smem (reusing As = 8KB = uex[32][64]).
__global__ __launch_bounds__(128, 5)
void moe_g1_kernel(const float* __restrict__ wg,
                   const float* __restrict__ wu) {
    const int e  = blockIdx.y >> 5;
    const int mt = blockIdx.y & 31;
    const int ne = g_cnt[e];
    if (mt * BM1 >= ne) return;
    const int nt = blockIdx.x;

    __shared__ float As[2][BM1][BK];   // 8 KB
    __shared__ float Bg[2][BN1][BK];   // 16 KB
    __shared__ float Bu[2][BN1][BK];   // 16 KB

    const int tid = threadIdx.x;
    const int lr = tid >> 3;       // load row base (0..15)
    const int cw = tid & 7;        // 16B chunk (0..7)

    int tok[2];
    #pragma unroll
    for (int j = 0; j < 2; j++) {
        const int slot = mt * BM1 + lr + j * 16;
        tok[j] = (slot < ne) ? g_tok[e][slot] : -1;
    }

    const float* wgE = wg + ((size_t)e * II + (size_t)nt * BN1) * HH;
    const float* wuE = wu + ((size_t)e * II + (size_t)nt * BN1) * HH;

    auto load_stage = [&](int k0, int buf) {
        #pragma unroll
        for (int j = 0; j < 2; j++) {
            const int r  = lr + j * 16;
            const int sc = ((cw ^ (r & 7)) << 2);
            const int ta = (tok[j] < 0) ? 0 : tok[j];
            cp16(&As[buf][r][sc], &g_x[ta][k0 + (cw << 2)], tok[j] >= 0);
        }
        #pragma unroll
        for (int j = 0; j < 4; j++) {
            const int r  = lr + j * 16;
            const int sc = ((cw ^ (r & 7)) << 2);
            cp16(&Bg[buf][r][sc], wgE + (size_t)r * HH + k0 + (cw << 2), true);
            cp16(&Bu[buf][r][sc], wuE + (size_t)r * HH + k0 + (cw << 2), true);
        }
    };

    const int warp = tid >> 5, lane = tid & 31;
    const bool isGate = (warp < 2);
    const int wn = (warp & 1) * 32;            // N offset within 64-wide tile
    const int grp = lane >> 2, tg = lane & 3;

    float acc[2][4][4];
    #pragma unroll
    for (int a = 0; a < 2; a++)
        #pragma unroll
        for (int b = 0; b < 4; b++)
            #pragma unroll
            for (int c = 0; c < 4; c++) acc[a][b][c] = 0.f;

    load_stage(0, 0); cp_commit();

    const int NK = HH / BK;   // 64
    for (int kt = 0; kt < NK; kt++) {
        const int buf = kt & 1;
        if (kt + 1 < NK) {
            load_stage((kt + 1) * BK, buf ^ 1); cp_commit();
            asm volatile("cp.async.wait_group 1;\n");
        } else {
            asm volatile("cp.async.wait_group 0;\n");
        }
        __syncthreads();

        const float* Bp = isGate ? &Bg[buf][0][0] : &Bu[buf][0][0];

        #pragma unroll
        for (int kk = 0; kk < BK; kk += 8) {
            // fragment rows/cols all have (idx & 7) == grp -> swizzle = ^grp
            const int c0 = (((kk >> 2)    ) ^ grp) << 2;
            const int c1 = (((kk >> 2) + 1) ^ grp) << 2;
            uint32_t a[2][4];
            #pragma unroll
            for (int mi = 0; mi < 2; mi++) {
                const int r0 = mi * 16 + grp, r1 = r0 + 8;
                a[mi][0] = __float_as_uint(As[buf][r0][c0 + tg]);
                a[mi][1] = __float_as_uint(As[buf][r1][c0 + tg]);
                a[mi][2] = __float_as_uint(As[buf][r0][c1 + tg]);
                a[mi][3] = __float_as_uint(As[buf][r1][c1 + tg]);
            }
            #pragma unroll
            for (int ni = 0; ni < 4; ni++) {
                const int col = wn + ni * 8 + grp;
                const uint32_t b0 = tf32r(Bp[col * BK + c0 + tg]);
                const uint32_t b1 = tf32r(Bp[col * BK + c1 + tg]);
                #pragma unroll
                for (int mi = 0; mi < 2; mi++)
                    mma_tf32(acc[mi][ni], a[mi], b0, b1);
            }
        }
        __syncthreads();
    }

    // -------- epilogue: exchange u via smem, gate warps do SwiGLU ------------
    // As (2*32*32 = 2048 floats = 8KB) is dead; reuse as uex[32][64].
    float (*uex)[BN1] = reinterpret_cast<float(*)[BN1]>(&As[0][0][0]);

    if (!isGate) {
        #pragma unroll
        for (int mi = 0; mi < 2; mi++) {
            #pragma unroll
            for (int h2 = 0; h2 < 2; h2++) {
                const int row = mi * 16 + grp + h2 * 8;
                #pragma unroll
                for (int ni = 0; ni < 4; ni++) {
                    const int col = wn + ni * 8 + tg * 2;
                    uex[row][col    ] = acc[mi][ni][h2 * 2 + 0];
                    uex[row][col + 1] = acc[mi][ni][h2 * 2 + 1];
                }
            }
        }
    }
    __syncthreads();
    if (isGate) {
        #pragma unroll
        for (int mi = 0; mi < 2; mi++) {
            #pragma unroll
            for (int h2 = 0; h2 < 2; h2++) {
                const int rloc = mi * 16 + grp + h2 * 8;
                const int slot = mt * BM1 + rloc;
                if (slot >= ne) continue;
                const float wt = g_wt[e][slot];
                float* hrow = g_h[g_prow[e][slot]];
                #pragma unroll
                for (int ni = 0; ni < 4; ni++) {
                    const int col = wn + ni * 8 + tg * 2;
                    const float u0 = uex[rloc][col];
                    const float u1 = uex[rloc][col + 1];
                    const float gg0 = acc[mi][ni][h2 * 2 + 0];
                    const float gg1 = acc[mi][ni][h2 * 2 + 1];
                    const float h0 = gg0 / (1.f + __expf(-gg0)) * u0 * wt;
                    const float h1 = gg1 / (1.f + __expf(-gg1)) * u1 * wt;
                    *reinterpret_cast<float2*>(hrow + nt * BN1 + col) =
                        make_float2(__uint_as_float(tf32r(h0)),
                                    __uint_as_float(tf32r(h1)));
                }
            }
        }
    }
}

// ---------------- kernel 3: down_proj GEMM -> atomicAdd into out -------------
// grid = (HH/BN2 = 16, EE * 32); CTA tile 32x128, 4 warps each 32(M)x32(N).
// smem: 2 x (A 32x32 + B 128x32) fp32 = 40 KB -> 5 CTAs/SM (acc=32 regs).
// A (g_h) pre-rounded -> no cvt.  Each out element receives exactly 2
// contributions; (0+a)+b == (0+b)+a in IEEE fp -> bit-deterministic.
__global__ __launch_bounds__(128, 5)
void moe_g2_kernel(const float* __restrict__ wd, float* __restrict__ out) {
    const int e  = blockIdx.y >> 5;
    const int mt = blockIdx.y & 31;
    const int ne = g_cnt[e];
    if (mt * BM2 >= ne) return;
    const int nt = blockIdx.x;

    __shared__ float As[2][BM2][BK];   // 8 KB
    __shared__ float Bs[2][BN2][BK];   // 32 KB

    const int tid = threadIdx.x;
    const int lr = tid >> 3;
    const int cw = tid & 7;

    int pr[2];
    #pragma unroll
    for (int j = 0; j < 2; j++) {
        const int slot = mt * BM2 + lr + j * 16;
        pr[j] = (slot < ne) ? g_prow[e][slot] : -1;
    }

    const float* wdE = wd + ((size_t)e * HH + (size_t)nt * BN2) * II;

    auto load_stage = [&](int k0, int buf) {
        #pragma unroll
        for (int j = 0; j < 2; j++) {
            const int r  = lr + j * 16;
            const int sc = ((cw ^ (r & 7)) << 2);
            const int pa = (pr[j] < 0) ? 0 : pr[j];
            cp16(&As[buf][r][sc], &g_h[pa][k0 + (cw << 2)], pr[j] >= 0);
        }
        #pragma unroll
        for (int j = 0; j < 8; j++) {
            const int r  = lr + j * 16;
            const int sc = ((cw ^ (r & 7)) << 2);
            cp16(&Bs[buf][r][sc], wdE + (size_t)r * II + k0 + (cw << 2), true);
        }
    };

    const int warp = tid >> 5, lane = tid & 31;
    const int wn = warp * 32;              // each warp owns 32 N-cols
    const int grp = lane >> 2, tg = lane & 3;

    float acc[2][4][4];
    #pragma unroll
    for (int a = 0; a < 2; a++)
        #pragma unroll
        for (int b = 0; b < 4; b++)
            #pragma unroll
            for (int c = 0; c < 4; c++) acc[a][b][c] = 0.f;

    load_stage(0, 0); cp_commit();

    const int NK = II / BK;   // 32
    for (int kt = 0; kt < NK; kt++) {
        const int buf = kt & 1;
        if (kt + 1 < NK) {
            load_stage((kt + 1) * BK, buf ^ 1); cp_commit();
            asm volatile("cp.async.wait_group 1;\n");
        } else {
            asm volatile("cp.async.wait_group 0;\n");
        }
        __syncthreads();

        #pragma unroll
        for (int kk = 0; kk < BK; kk += 8) {
            const int c0 = (((kk >> 2)    ) ^ grp) << 2;
            const int c1 = (((kk >> 2) + 1) ^ grp) << 2;
            uint32_t a[2][4];
            #pragma unroll
            for (int mi = 0; mi < 2; mi++) {
                const int r0 = mi * 16 + grp, r1 = r0 + 8;
                a[mi][0] = __float_as_uint(As[buf][r0][c0 + tg]);
                a[mi][1] = __float_as_uint(As[buf][r1][c0 + tg]);
                a[mi][2] = __float_as_uint(As[buf][r0][c1 + tg]);
                a[mi][3] = __float_as_uint(As[buf][r1][c1 + tg]);
            }
            #pragma unroll
            for (int ni = 0; ni < 4; ni++) {
                const int col = wn + ni * 8 + grp;
                const uint32_t b0 = tf32r(Bs[buf][col][c0 + tg]);
                const uint32_t b1 = tf32r(Bs[buf][col][c1 + tg]);
                #pragma unroll
                for (int mi = 0; mi < 2; mi++)
                    mma_tf32(acc[mi][ni], a[mi], b0, b1);
            }
        }
        __syncthreads();
    }

    // epilogue: atomic accumulate into out (exactly 2 contributions/element)
    #pragma unroll
    for (int mi = 0; mi < 2; mi++) {
        #pragma unroll
        for (int h2 = 0; h2 < 2; h2++) {
            const int rloc = mi * 16 + grp + h2 * 8;
            const int slot = mt * BM2 + rloc;
            if (slot >= ne) continue;
            const int t = g_prow[e][slot] >> 1;
            float* orow = out + (size_t)t * HH + nt * BN2;
            #pragma unroll
            for (int ni = 0; ni < 4; ni++) {
                const int col = wn + ni * 8 + tg * 2;
                atomicAdd(orow + col,     acc[mi][ni][h2 * 2 + 0]);
                atomicAdd(orow + col + 1, acc[mi][ni][h2 * 2 + 1]);
            }
        }
    }
}

// ---------------- launch -----------------------------------------------------
extern "C" void kernel_launch(void* const* d_in, const int* in_sizes, int n_in,
                              void* d_out, int out_size) {
    const float* x  = (const float*)d_in[0];   // [T, H]
    const float* gw = (const float*)d_in[1];   // [E, H] router
    const float* wg = (const float*)d_in[2];   // [E, I, H] gate_proj
    const float* wu = (const float*)d_in[3];   // [E, I, H] up_proj
    const float* wd = (const float*)d_in[4];   // [E, H, I] down_proj
    float* out = (float*)d_out;                // [T, H]

    zero_kernel<<<(TT * HH / 4) / 256, 256>>>(out);
    router_kernel<<<TT / RT, 128>>>(x, gw);
    moe_g1_kernel<<<dim3(II / BN1, EE * 32), 128>>>(wg, wu);
    moe_g2_kernel<<<dim3(HH / BN2, EE * 32), 128>>>(wd, out);
}

// round 17
// speedup vs baseline: 2.0425x; 1.0213x over previous
#include <cuda_runtime.h>
#include <cuda.h>
#include <cstdint>

// Shapes (fixed by the problem)
#define TT 1024   // tokens
#define HH 2048   // hidden
#define II 1024   // intermediate
#define EE 32     // experts
// GEMM tiling
#define BM1 32    // g1 CTA M-tile
#define BM2 32    // g2 CTA M-tile
#define BN1 64    // g1 CTA N-tile (gate & up each)
#define BN2 128   // g2 CTA N-tile
#define BK 32
#define RT 4      // tokens per router block

// ---------------- device scratch (static: no allocations allowed) ----------
__device__ int   g_cnt[EE];
__device__ int   g_tok [EE][TT];
__device__ float g_wt  [EE][TT];
__device__ int   g_prow[EE][TT];
__device__ float g_x[TT][HH];       // tf32-rounded activations: 8 MB
__device__ float g_h[TT * 2][II];   // tf32-rounded silu(g)*u*wt per pair: 8 MB

// ---------------- helpers ---------------------------------------------------
__device__ __forceinline__ uint32_t tf32r(float v) {
    uint32_t r;
    asm("cvt.rna.tf32.f32 %0, %1;" : "=r"(r) : "f"(v));
    return r;
}

__device__ __forceinline__ void mma_tf32(float* d, const uint32_t* a,
                                         uint32_t b0, uint32_t b1) {
    asm volatile(
        "mma.sync.aligned.m16n8k8.row.col.f32.tf32.tf32.f32 "
        "{%0,%1,%2,%3}, {%4,%5,%6,%7}, {%8,%9}, {%0,%1,%2,%3};\n"
        : "+f"(d[0]), "+f"(d[1]), "+f"(d[2]), "+f"(d[3])
        : "r"(a[0]), "r"(a[1]), "r"(a[2]), "r"(a[3]), "r"(b0), "r"(b1));
}

// 16B cp.async with zero-fill predicate (CUTLASS zfill form)
__device__ __forceinline__ void cp16(void* smem, const void* gmem, bool pred) {
    uint32_t sa = (uint32_t)__cvta_generic_to_shared(smem);
    int sz = pred ? 16 : 0;
    asm volatile("cp.async.cg.shared.global [%0], [%1], 16, %2;\n"
                 :: "r"(sa), "l"(gmem), "r"(sz));
}
__device__ __forceinline__ void cp_commit() {
    asm volatile("cp.async.commit_group;\n");
}

// ---- mbarrier + TMA helpers -------------------------------------------------
__device__ __forceinline__ void mbar_init(uint32_t addr, uint32_t count) {
    asm volatile("mbarrier.init.shared.b64 [%0], %1;" :: "r"(addr), "r"(count) : "memory");
}
__device__ __forceinline__ void mbar_expect_tx(uint32_t addr, uint32_t bytes) {
    asm volatile("mbarrier.arrive.expect_tx.shared.b64 _, [%0], %1;"
                 :: "r"(addr), "r"(bytes) : "memory");
}
__device__ __forceinline__ void mbar_wait(uint32_t addr, uint32_t parity) {
    asm volatile(
        "{\n\t"
        ".reg .pred P;\n\t"
        "WAIT_%=:\n\t"
        "mbarrier.try_wait.parity.acquire.cta.shared::cta.b64 P, [%0], %1;\n\t"
        "@P bra DONE_%=;\n\t"
        "bra WAIT_%=;\n\t"
        "DONE_%=:\n\t"
        "}"
        :: "r"(addr), "r"(parity) : "memory");
}
__device__ __forceinline__ void tma_load_2d(uint32_t smem_addr,
                                            const CUtensorMap* tmap,
                                            int cx, int cy, uint32_t mbar) {
    asm volatile(
        "cp.async.bulk.tensor.2d.shared::cta.global.tile.mbarrier::complete_tx::bytes "
        "[%0], [%1, {%2, %3}], [%4];"
        :: "r"(smem_addr), "l"(tmap), "r"(cx), "r"(cy), "r"(mbar) : "memory");
}

// ---------------- kernel 0: zero out + counters ------------------------------
__global__ __launch_bounds__(256)
void zero_kernel(float* __restrict__ out) {
    if (blockIdx.x == 0 && threadIdx.x < EE) g_cnt[threadIdx.x] = 0;
    const int i = blockIdx.x * 256 + threadIdx.x;   // TT*HH/4 float4s
    reinterpret_cast<float4*>(out)[i] = make_float4(0.f, 0.f, 0.f, 0.f);
}

// ---------------- kernel 1: router + tf32 pre-round of x ---------------------
__global__ __launch_bounds__(128)
void router_kernel(const float* __restrict__ x, const float* __restrict__ gw) {
    __shared__ float xs[RT][HH];     // 32 KB
    __shared__ float lg[RT][EE];

    const int t0 = blockIdx.x * RT;
    for (int i = threadIdx.x; i < RT * (HH / 4); i += 128) {
        const int rt = i >> 9;             // HH/4 = 512
        const int c  = i & 511;
        reinterpret_cast<float4*>(xs[rt])[c] =
            reinterpret_cast<const float4*>(x + (size_t)(t0 + rt) * HH)[c];
    }
    __syncthreads();

    {
        const float* xf = &xs[0][0];
        float* gx = &g_x[t0][0];
        for (int i = threadIdx.x * 4; i < RT * HH; i += 128 * 4) {
            float4 v = *reinterpret_cast<const float4*>(xf + i);
            v.x = __uint_as_float(tf32r(v.x));
            v.y = __uint_as_float(tf32r(v.y));
            v.z = __uint_as_float(tf32r(v.z));
            v.w = __uint_as_float(tf32r(v.w));
            *reinterpret_cast<float4*>(gx + i) = v;
        }
    }

    const int warp = threadIdx.x >> 5, lane = threadIdx.x & 31;
    const float4* xv = reinterpret_cast<const float4*>(xs[warp]);
    for (int e = 0; e < EE; e++) {
        const float4* wv = reinterpret_cast<const float4*>(gw + (size_t)e * HH);
        float acc = 0.f;
        for (int k = lane; k < HH / 4; k += 32) {
            float4 a = xv[k], b = wv[k];
            acc += a.x * b.x + a.y * b.y + a.z * b.z + a.w * b.w;
        }
        #pragma unroll
        for (int o = 16; o; o >>= 1) acc += __shfl_xor_sync(0xffffffffu, acc, o);
        if (lane == 0) lg[warp][e] = acc;
    }
    if (lane == 0) {
        const int t = t0 + warp;
        float v0 = -1e30f, v1 = -1e30f; int i0 = 0, i1 = 0;
        for (int e = 0; e < EE; e++) {
            const float v = lg[warp][e];
            if (v > v0)      { v1 = v0; i1 = i0; v0 = v; i0 = e; }
            else if (v > v1) { v1 = v;  i1 = e; }
        }
        const float w0 = 1.f / (1.f + expf(v1 - v0));
        const float w1 = 1.f - w0;
        int s0 = atomicAdd(&g_cnt[i0], 1);
        g_tok[i0][s0] = t; g_wt[i0][s0] = w0; g_prow[i0][s0] = 2 * t;
        int s1 = atomicAdd(&g_cnt[i1], 1);
        g_tok[i1][s1] = t; g_wt[i1][s1] = w1; g_prow[i1][s1] = 2 * t + 1;
    }
}

// ---------------- kernel 2: fused gate&up GEMM + SwiGLU (unchanged R15) ------
__global__ __launch_bounds__(128, 5)
void moe_g1_kernel(const float* __restrict__ wg,
                   const float* __restrict__ wu) {
    const int e  = blockIdx.y >> 5;
    const int mt = blockIdx.y & 31;
    const int ne = g_cnt[e];
    if (mt * BM1 >= ne) return;
    const int nt = blockIdx.x;

    __shared__ float As[2][BM1][BK];   // 8 KB
    __shared__ float Bg[2][BN1][BK];   // 16 KB
    __shared__ float Bu[2][BN1][BK];   // 16 KB

    const int tid = threadIdx.x;
    const int lr = tid >> 3;
    const int cw = tid & 7;

    int tok[2];
    #pragma unroll
    for (int j = 0; j < 2; j++) {
        const int slot = mt * BM1 + lr + j * 16;
        tok[j] = (slot < ne) ? g_tok[e][slot] : -1;
    }

    const float* wgE = wg + ((size_t)e * II + (size_t)nt * BN1) * HH;
    const float* wuE = wu + ((size_t)e * II + (size_t)nt * BN1) * HH;

    auto load_stage = [&](int k0, int buf) {
        #pragma unroll
        for (int j = 0; j < 2; j++) {
            const int r  = lr + j * 16;
            const int sc = ((cw ^ (r & 7)) << 2);
            const int ta = (tok[j] < 0) ? 0 : tok[j];
            cp16(&As[buf][r][sc], &g_x[ta][k0 + (cw << 2)], tok[j] >= 0);
        }
        #pragma unroll
        for (int j = 0; j < 4; j++) {
            const int r  = lr + j * 16;
            const int sc = ((cw ^ (r & 7)) << 2);
            cp16(&Bg[buf][r][sc], wgE + (size_t)r * HH + k0 + (cw << 2), true);
            cp16(&Bu[buf][r][sc], wuE + (size_t)r * HH + k0 + (cw << 2), true);
        }
    };

    const int warp = tid >> 5, lane = tid & 31;
    const bool isGate = (warp < 2);
    const int wn = (warp & 1) * 32;
    const int grp = lane >> 2, tg = lane & 3;

    float acc[2][4][4];
    #pragma unroll
    for (int a = 0; a < 2; a++)
        #pragma unroll
        for (int b = 0; b < 4; b++)
            #pragma unroll
            for (int c = 0; c < 4; c++) acc[a][b][c] = 0.f;

    load_stage(0, 0); cp_commit();

    const int NK = HH / BK;   // 64
    for (int kt = 0; kt < NK; kt++) {
        const int buf = kt & 1;
        if (kt + 1 < NK) {
            load_stage((kt + 1) * BK, buf ^ 1); cp_commit();
            asm volatile("cp.async.wait_group 1;\n");
        } else {
            asm volatile("cp.async.wait_group 0;\n");
        }
        __syncthreads();

        const float* Bp = isGate ? &Bg[buf][0][0] : &Bu[buf][0][0];

        #pragma unroll
        for (int kk = 0; kk < BK; kk += 8) {
            const int c0 = (((kk >> 2)    ) ^ grp) << 2;
            const int c1 = (((kk >> 2) + 1) ^ grp) << 2;
            uint32_t a[2][4];
            #pragma unroll
            for (int mi = 0; mi < 2; mi++) {
                const int r0 = mi * 16 + grp, r1 = r0 + 8;
                a[mi][0] = __float_as_uint(As[buf][r0][c0 + tg]);
                a[mi][1] = __float_as_uint(As[buf][r1][c0 + tg]);
                a[mi][2] = __float_as_uint(As[buf][r0][c1 + tg]);
                a[mi][3] = __float_as_uint(As[buf][r1][c1 + tg]);
            }
            #pragma unroll
            for (int ni = 0; ni < 4; ni++) {
                const int col = wn + ni * 8 + grp;
                const uint32_t b0 = tf32r(Bp[col * BK + c0 + tg]);
                const uint32_t b1 = tf32r(Bp[col * BK + c1 + tg]);
                #pragma unroll
                for (int mi = 0; mi < 2; mi++)
                    mma_tf32(acc[mi][ni], a[mi], b0, b1);
            }
        }
        __syncthreads();
    }

    float (*uex)[BN1] = reinterpret_cast<float(*)[BN1]>(&As[0][0][0]);

    if (!isGate) {
        #pragma unroll
        for (int mi = 0; mi < 2; mi++) {
            #pragma unroll
            for (int h2 = 0; h2 < 2; h2++) {
                const int row = mi * 16 + grp + h2 * 8;
                #pragma unroll
                for (int ni = 0; ni < 4; ni++) {
                    const int col = wn + ni * 8 + tg * 2;
                    uex[row][col    ] = acc[mi][ni][h2 * 2 + 0];
                    uex[row][col + 1] = acc[mi][ni][h2 * 2 + 1];
                }
            }
        }
    }
    __syncthreads();
    if (isGate) {
        #pragma unroll
        for (int mi = 0; mi < 2; mi++) {
            #pragma unroll
            for (int h2 = 0; h2 < 2; h2++) {
                const int rloc = mi * 16 + grp + h2 * 8;
                const int slot = mt * BM1 + rloc;
                if (slot >= ne) continue;
                const float wt = g_wt[e][slot];
                float* hrow = g_h[g_prow[e][slot]];
                #pragma unroll
                for (int ni = 0; ni < 4; ni++) {
                    const int col = wn + ni * 8 + tg * 2;
                    const float u0 = uex[rloc][col];
                    const float u1 = uex[rloc][col + 1];
                    const float gg0 = acc[mi][ni][h2 * 2 + 0];
                    const float gg1 = acc[mi][ni][h2 * 2 + 1];
                    const float h0 = gg0 / (1.f + __expf(-gg0)) * u0 * wt;
                    const float h1 = gg1 / (1.f + __expf(-gg1)) * u1 * wt;
                    *reinterpret_cast<float2*>(hrow + nt * BN1 + col) =
                        make_float2(__uint_as_float(tf32r(h0)),
                                    __uint_as_float(tf32r(h1)));
                }
            }
        }
    }
}

// ---------------- kernel 3: down_proj GEMM, B via TMA -> atomicAdd -----------
// grid = (HH/BN2 = 16, EE * 32); CTA tile 32x128, 4 warps each 32(M)x32(N).
// B tile (128 rows x 128B) loaded per stage by ONE cp.async.bulk.tensor.2d
// (SW128 swizzle == the existing chunk^(row&7) XOR; read code unchanged).
// A (gathered g_h rows) stays per-thread cp.async.
__global__ __launch_bounds__(128, 5)
void moe_g2_kernel(const __grid_constant__ CUtensorMap tmap,
                   float* __restrict__ out) {
    const int e  = blockIdx.y >> 5;
    const int mt = blockIdx.y & 31;
    const int ne = g_cnt[e];
    if (mt * BM2 >= ne) return;
    const int nt = blockIdx.x;

    __shared__ float As[2][BM2][BK];                       // 8 KB
    __shared__ __align__(1024) float Bs[2][BN2][BK];       // 32 KB
    __shared__ __align__(8) unsigned long long s_mbar[2];

    const int tid = threadIdx.x;
    const int lr = tid >> 3;
    const int cw = tid & 7;

    int pr[2];
    #pragma unroll
    for (int j = 0; j < 2; j++) {
        const int slot = mt * BM2 + lr + j * 16;
        pr[j] = (slot < ne) ? g_prow[e][slot] : -1;
    }

    const uint32_t mb0 = (uint32_t)__cvta_generic_to_shared(&s_mbar[0]);
    const uint32_t mb1 = (uint32_t)__cvta_generic_to_shared(&s_mbar[1]);
    const int browbase = e * HH + nt * BN2;   // row coord in [E*HH, II] view

    auto load_A = [&](int k0, int buf) {
        #pragma unroll
        for (int j = 0; j < 2; j++) {
            const int r  = lr + j * 16;
            const int sc = ((cw ^ (r & 7)) << 2);
            const int pa = (pr[j] < 0) ? 0 : pr[j];
            cp16(&As[buf][r][sc], &g_h[pa][k0 + (cw << 2)], pr[j] >= 0);
        }
    };
    auto load_B = [&](int k0, int buf) {
        if (tid == 0) {
            const uint32_t mb = buf ? mb1 : mb0;
            mbar_expect_tx(mb, BN2 * BK * 4);   // 16384 bytes
            tma_load_2d((uint32_t)__cvta_generic_to_shared(&Bs[buf][0][0]),
                        &tmap, k0, browbase, mb);
        }
    };

    if (tid == 0) { mbar_init(mb0, 1); mbar_init(mb1, 1); }
    load_A(0, 0); cp_commit();
    __syncthreads();                 // mbarrier init visible to all
    load_B(0, 0);

    const int warp = tid >> 5, lane = tid & 31;
    const int wn = warp * 32;
    const int grp = lane >> 2, tg = lane & 3;

    float acc[2][4][4];
    #pragma unroll
    for (int a = 0; a < 2; a++)
        #pragma unroll
        for (int b = 0; b < 4; b++)
            #pragma unroll
            for (int c = 0; c < 4; c++) acc[a][b][c] = 0.f;

    int phase0 = 0, phase1 = 0;

    const int NK = II / BK;   // 32
    for (int kt = 0; kt < NK; kt++) {
        const int buf = kt & 1;
        if (kt + 1 < NK) {
            load_A((kt + 1) * BK, buf ^ 1); cp_commit();
            load_B((kt + 1) * BK, buf ^ 1);
            asm volatile("cp.async.wait_group 1;\n");
        } else {
            asm volatile("cp.async.wait_group 0;\n");
        }
        // wait B tile for this stage
        if (buf == 0) { mbar_wait(mb0, phase0); phase0 ^= 1; }
        else          { mbar_wait(mb1, phase1); phase1 ^= 1; }
        __syncthreads();

        #pragma unroll
        for (int kk = 0; kk < BK; kk += 8) {
            const int c0 = (((kk >> 2)    ) ^ grp) << 2;
            const int c1 = (((kk >> 2) + 1) ^ grp) << 2;
            uint32_t a[2][4];
            #pragma unroll
            for (int mi = 0; mi < 2; mi++) {
                const int r0 = mi * 16 + grp, r1 = r0 + 8;
                a[mi][0] = __float_as_uint(As[buf][r0][c0 + tg]);
                a[mi][1] = __float_as_uint(As[buf][r1][c0 + tg]);
                a[mi][2] = __float_as_uint(As[buf][r0][c1 + tg]);
                a[mi][3] = __float_as_uint(As[buf][r1][c1 + tg]);
            }
            #pragma unroll
            for (int ni = 0; ni < 4; ni++) {
                const int col = wn + ni * 8 + grp;
                const uint32_t b0 = tf32r(Bs[buf][col][c0 + tg]);
                const uint32_t b1 = tf32r(Bs[buf][col][c1 + tg]);
                #pragma unroll
                for (int mi = 0; mi < 2; mi++)
                    mma_tf32(acc[mi][ni], a[mi], b0, b1);
            }
        }
        __syncthreads();
    }

    // epilogue: atomic accumulate into out (exactly 2 contributions/element)
    #pragma unroll
    for (int mi = 0; mi < 2; mi++) {
        #pragma unroll
        for (int h2 = 0; h2 < 2; h2++) {
            const int rloc = mi * 16 + grp + h2 * 8;
            const int slot = mt * BM2 + rloc;
            if (slot >= ne) continue;
            const int t = g_prow[e][slot] >> 1;
            float* orow = out + (size_t)t * HH + nt * BN2;
            #pragma unroll
            for (int ni = 0; ni < 4; ni++) {
                const int col = wn + ni * 8 + tg * 2;
                atomicAdd(orow + col,     acc[mi][ni][h2 * 2 + 0]);
                atomicAdd(orow + col + 1, acc[mi][ni][h2 * 2 + 1]);
            }
        }
    }
}

// ---------------- launch -----------------------------------------------------
typedef CUresult (*tme_fn_t)(CUtensorMap*, CUtensorMapDataType, cuuint32_t,
                             void*, const cuuint64_t*, const cuuint64_t*,
                             const cuuint32_t*, const cuuint32_t*,
                             CUtensorMapInterleave, CUtensorMapSwizzle,
                             CUtensorMapL2promotion, CUtensorMapFloatOOBfill);

extern "C" void kernel_launch(void* const* d_in, const int* in_sizes, int n_in,
                              void* d_out, int out_size) {
    const float* x  = (const float*)d_in[0];   // [T, H]
    const float* gw = (const float*)d_in[1];   // [E, H] router
    const float* wg = (const float*)d_in[2];   // [E, I, H] gate_proj
    const float* wu = (const float*)d_in[3];   // [E, I, H] up_proj
    const float* wd = (const float*)d_in[4];   // [E, H, I] down_proj
    float* out = (float*)d_out;                // [T, H]

    // Tensor map for wd viewed as 2D [E*HH rows, II cols] row-major.
    tme_fn_t encode = nullptr;
    cudaGetDriverEntryPoint("cuTensorMapEncodeTiled", (void**)&encode,
                            cudaEnableDefault, nullptr);
    CUtensorMap tmap;
    {
        cuuint64_t dims[2]    = { (cuuint64_t)II, (cuuint64_t)(EE * HH) };
        cuuint64_t strides[1] = { (cuuint64_t)II * sizeof(float) };
        cuuint32_t box[2]     = { BK, BN2 };         // 32 floats x 128 rows
        cuuint32_t estr[2]    = { 1, 1 };
        encode(&tmap, CU_TENSOR_MAP_DATA_TYPE_FLOAT32, 2, (void*)wd,
               dims, strides, box, estr,
               CU_TENSOR_MAP_INTERLEAVE_NONE, CU_TENSOR_MAP_SWIZZLE_128B,
               CU_TENSOR_MAP_L2_PROMOTION_L2_128B,
               CU_TENSOR_MAP_FLOAT_OOB_FILL_NONE);
    }

    zero_kernel<<<(TT * HH / 4) / 256, 256>>>(out);
    router_kernel<<<TT / RT, 128>>>(x, gw);
    moe_g1_kernel<<<dim3(II / BN1, EE * 32), 128>>>(wg, wu);
    moe_g2_kernel<<<dim3(HH / BN2, EE * 32), 128>>>(tmap, out);
}